// round 1
// baseline (speedup 1.0000x reference)
#include <cuda_runtime.h>
#include <cstdint>

#define N_NODES 50000
#define N_EDGES 800000
#define IN_F    128
#define OUT_F   256

// Scratch for aggregated messages (25.6 MB) — __device__ global (no allocs allowed).
__device__ float g_agg[(size_t)N_NODES * IN_F];

// ---------------------------------------------------------------------------
// Kernel 1: zero the aggregation buffer (float4 grid-stride).
// ---------------------------------------------------------------------------
__global__ void zero_agg_kernel() {
    const int n4 = (N_NODES * IN_F) / 4;   // 1.6M float4
    float4 z = make_float4(0.f, 0.f, 0.f, 0.f);
    float4* p = reinterpret_cast<float4*>(g_agg);
    for (int i = blockIdx.x * blockDim.x + threadIdx.x; i < n4;
         i += gridDim.x * blockDim.x)
        p[i] = z;
}

// ---------------------------------------------------------------------------
// Kernel 2: SpMM scatter. One warp handles EDGES_PER_WARP edges.
// Per edge: coalesced 512B gather of x[col], scale by val, vectorized
// red.global.add.v4.f32 into g_agg[row].
// ---------------------------------------------------------------------------
#define EDGES_PER_WARP 4

__global__ void spmm_scatter_kernel(const float* __restrict__ x,
                                    const int*   __restrict__ erow,
                                    const int*   __restrict__ ecol,
                                    const float* __restrict__ eval) {
    const int lane = threadIdx.x & 31;
    const int warp = (blockIdx.x * (blockDim.x >> 5)) + (threadIdx.x >> 5);
    const int e0 = warp * EDGES_PER_WARP;

    #pragma unroll
    for (int i = 0; i < EDGES_PER_WARP; i++) {
        const int e = e0 + i;
        if (e >= N_EDGES) return;
        const int   r = __ldg(erow + e);
        const int   c = __ldg(ecol + e);
        const float v = __ldg(eval + e);

        const float4 xv =
            __ldg(reinterpret_cast<const float4*>(x + (size_t)c * IN_F) + lane);

        float* dst = g_agg + (size_t)r * IN_F + lane * 4;
        asm volatile("red.global.add.v4.f32 [%0], {%1, %2, %3, %4};"
                     :: "l"(dst),
                        "f"(xv.x * v), "f"(xv.y * v),
                        "f"(xv.z * v), "f"(xv.w * v)
                     : "memory");
    }
}

// ---------------------------------------------------------------------------
// Kernel 3: dense transform  out = agg @ W + b.
// Block: 32 rows x 256 cols, 512 threads, 4x4 micro-tile per thread.
// W (128KB) staged whole in dynamic smem; agg tile transposed [k][row] in
// static smem so the 4-row a-fragment is a single LDS.128.
// ---------------------------------------------------------------------------
#define GEMM_THREADS 512
#define TILE_M       32

__global__ __launch_bounds__(GEMM_THREADS, 1)
void gemm_bias_kernel(const float* __restrict__ W,
                      const float* __restrict__ bias,
                      float*       __restrict__ out) {
    extern __shared__ float Ws[];                 // [IN_F][OUT_F] = 128KB
    __shared__ float As[IN_F * TILE_M];           // [k][row], 16KB

    const int t = threadIdx.x;
    const int rowbase = blockIdx.x * TILE_M;

    // Stage W: 32768 floats = 8192 float4, 16 per thread, coalesced.
    {
        const float4* W4  = reinterpret_cast<const float4*>(W);
        float4*       Ws4 = reinterpret_cast<float4*>(Ws);
        #pragma unroll
        for (int i = 0; i < (IN_F * OUT_F / 4) / GEMM_THREADS; i++)
            Ws4[t + i * GEMM_THREADS] = W4[t + i * GEMM_THREADS];
    }

    // Stage agg tile transposed: As[k*32 + rl] = agg[rowbase+rl][k].
    // Lanes within a warp take consecutive rl -> conflict-free STS.
    #pragma unroll
    for (int i = 0; i < (IN_F * TILE_M) / GEMM_THREADS; i++) {
        const int idx = t + i * GEMM_THREADS;
        const int rl = idx & (TILE_M - 1);
        const int k  = idx / TILE_M;
        const int row = rowbase + rl;
        As[k * TILE_M + rl] =
            (row < N_NODES) ? g_agg[(size_t)row * IN_F + k] : 0.f;
    }
    __syncthreads();

    // Thread micro-tile: 4 rows x 4 cols.
    const int cg = t & 63;        // 64 col groups * 4 = 256 cols
    const int rg = t >> 6;        // 8 row groups  * 4 = 32 rows
    const int c0 = cg * 4;
    const int r0 = rg * 4;

    float acc00 = 0.f, acc01 = 0.f, acc02 = 0.f, acc03 = 0.f;
    float acc10 = 0.f, acc11 = 0.f, acc12 = 0.f, acc13 = 0.f;
    float acc20 = 0.f, acc21 = 0.f, acc22 = 0.f, acc23 = 0.f;
    float acc30 = 0.f, acc31 = 0.f, acc32 = 0.f, acc33 = 0.f;

    #pragma unroll 8
    for (int k = 0; k < IN_F; k++) {
        const float4 a = *reinterpret_cast<const float4*>(&As[k * TILE_M + r0]);
        const float4 w = *reinterpret_cast<const float4*>(&Ws[k * OUT_F + c0]);

        acc00 += a.x * w.x; acc01 += a.x * w.y; acc02 += a.x * w.z; acc03 += a.x * w.w;
        acc10 += a.y * w.x; acc11 += a.y * w.y; acc12 += a.y * w.z; acc13 += a.y * w.w;
        acc20 += a.z * w.x; acc21 += a.z * w.y; acc22 += a.z * w.z; acc23 += a.z * w.w;
        acc30 += a.w * w.x; acc31 += a.w * w.y; acc32 += a.w * w.z; acc33 += a.w * w.w;
    }

    const float4 bv = *reinterpret_cast<const float4*>(&bias[c0]);

    float4 o;
    int row = rowbase + r0;
    if (row < N_NODES) {
        o = make_float4(acc00 + bv.x, acc01 + bv.y, acc02 + bv.z, acc03 + bv.w);
        *reinterpret_cast<float4*>(&out[(size_t)row * OUT_F + c0]) = o;
    }
    row++;
    if (row < N_NODES) {
        o = make_float4(acc10 + bv.x, acc11 + bv.y, acc12 + bv.z, acc13 + bv.w);
        *reinterpret_cast<float4*>(&out[(size_t)row * OUT_F + c0]) = o;
    }
    row++;
    if (row < N_NODES) {
        o = make_float4(acc20 + bv.x, acc21 + bv.y, acc22 + bv.z, acc23 + bv.w);
        *reinterpret_cast<float4*>(&out[(size_t)row * OUT_F + c0]) = o;
    }
    row++;
    if (row < N_NODES) {
        o = make_float4(acc30 + bv.x, acc31 + bv.y, acc32 + bv.z, acc33 + bv.w);
        *reinterpret_cast<float4*>(&out[(size_t)row * OUT_F + c0]) = o;
    }
}

// ---------------------------------------------------------------------------
// Launch
// ---------------------------------------------------------------------------
extern "C" void kernel_launch(void* const* d_in, const int* in_sizes, int n_in,
                              void* d_out, int out_size) {
    const float* x    = (const float*)d_in[0];
    const int*   erow = (const int*)  d_in[1];
    const int*   ecol = (const int*)  d_in[2];
    const float* eval = (const float*)d_in[3];
    const float* W    = (const float*)d_in[4];
    const float* bias = (const float*)d_in[5];
    float* out = (float*)d_out;

    // 1. zero scratch
    zero_agg_kernel<<<2048, 256>>>();

    // 2. SpMM scatter: 200000 warps / 8 warps-per-block = 25000 blocks
    const int warps_needed  = (N_EDGES + EDGES_PER_WARP - 1) / EDGES_PER_WARP;
    const int spmm_blocks   = (warps_needed + 7) / 8;
    spmm_scatter_kernel<<<spmm_blocks, 256>>>(x, erow, ecol, eval);

    // 3. GEMM + bias (needs >48KB dynamic smem; idempotent attr set each call)
    const int gemm_smem = IN_F * OUT_F * (int)sizeof(float);   // 128KB
    cudaFuncSetAttribute(gemm_bias_kernel,
                         cudaFuncAttributeMaxDynamicSharedMemorySize, gemm_smem);
    const int gemm_blocks = (N_NODES + TILE_M - 1) / TILE_M;   // 1563
    gemm_bias_kernel<<<gemm_blocks, GEMM_THREADS, gemm_smem>>>(W, bias, out);
}

// round 3
// speedup vs baseline: 1.4828x; 1.4828x over previous
#include <cuda_runtime.h>
#include <cuda_bf16.h>
#include <cstdint>

#define N_NODES 50000
#define N_EDGES 800000
#define IN_F    128
#define OUT_F   256
#define PITCH   136   // bf16 per padded row: 272B = 68 words, 68 mod 32 = 4 -> conflict-free frags

// ---------------------------------------------------------------------------
// Device scratch (no allocs allowed)
// ---------------------------------------------------------------------------
__device__ float g_agg[(size_t)N_NODES * IN_F];                    // 25.6 MB
// W^T hi/lo bf16 images, [n][k] row-major with pitch PITCH.
__device__ __align__(16) __nv_bfloat16 g_Bhi[OUT_F * PITCH];       // 68 KB
__device__ __align__(16) __nv_bfloat16 g_Blo[OUT_F * PITCH];       // 68 KB

// ---------------------------------------------------------------------------
// Kernel 1: zero agg + convert W -> padded bf16 hi/lo images of W^T.
// ---------------------------------------------------------------------------
__global__ void prep_kernel(const float* __restrict__ W) {
    const int tid = blockIdx.x * blockDim.x + threadIdx.x;
    const int n4 = (N_NODES * IN_F) / 4;
    float4 z = make_float4(0.f, 0.f, 0.f, 0.f);
    float4* p = reinterpret_cast<float4*>(g_agg);
    for (int i = tid; i < n4; i += gridDim.x * blockDim.x) p[i] = z;

    if (blockIdx.x < 32) {   // 32 blk * 256 thr * 4 = 32768 = IN_F*OUT_F
        const int base = (blockIdx.x * 256 + threadIdx.x) * 4;    // idx = k*256+n
        const float4 w = *reinterpret_cast<const float4*>(W + base);
        const float f[4] = {w.x, w.y, w.z, w.w};
        #pragma unroll
        for (int j = 0; j < 4; j++) {
            const int idx = base + j;
            const int k = idx >> 8;        // 0..127
            const int n = idx & 255;       // 0..255
            const __nv_bfloat16 h = __float2bfloat16(f[j]);
            const __nv_bfloat16 l = __float2bfloat16(f[j] - __bfloat162float(h));
            g_Bhi[n * PITCH + k] = h;
            g_Blo[n * PITCH + k] = l;
        }
    }
}

// ---------------------------------------------------------------------------
// Kernel 2: SpMM scatter. One warp per 4 edges, red.global.add.v4.f32.
// ---------------------------------------------------------------------------
#define EDGES_PER_WARP 4

__global__ void spmm_scatter_kernel(const float* __restrict__ x,
                                    const int*   __restrict__ erow,
                                    const int*   __restrict__ ecol,
                                    const float* __restrict__ eval) {
    const int lane = threadIdx.x & 31;
    const int warp = (blockIdx.x * (blockDim.x >> 5)) + (threadIdx.x >> 5);
    const int e0 = warp * EDGES_PER_WARP;

    #pragma unroll
    for (int i = 0; i < EDGES_PER_WARP; i++) {
        const int e = e0 + i;
        if (e >= N_EDGES) return;
        const int   r = __ldg(erow + e);
        const int   c = __ldg(ecol + e);
        const float v = __ldg(eval + e);

        const float4 xv =
            __ldg(reinterpret_cast<const float4*>(x + (size_t)c * IN_F) + lane);

        float* dst = g_agg + (size_t)r * IN_F + lane * 4;
        asm volatile("red.global.add.v4.f32 [%0], {%1, %2, %3, %4};"
                     :: "l"(dst),
                        "f"(xv.x * v), "f"(xv.y * v),
                        "f"(xv.z * v), "f"(xv.w * v)
                     : "memory");
    }
}

// ---------------------------------------------------------------------------
// Kernel 3: mma.sync bf16 split-precision GEMM + bias.
//   out[128,256] = Ahi@Bhi + Ahi@Blo + Alo@Bhi + b   (fp32 accum)
// 256 threads = 8 warps (2x4), warp tile 64x64, mma.m16n8k16.
// ---------------------------------------------------------------------------
#define GT 256
#define SM_BIAS 0
#define SM_AHI  1024
#define SM_ALO  (SM_AHI + 128 * PITCH * 2)          // +34816
#define SM_BHI  (SM_ALO + 128 * PITCH * 2)
#define SM_BLO  (SM_BHI + OUT_F * PITCH * 2)        // +69632
#define SM_TOT  (SM_BLO + OUT_F * PITCH * 2)        // 209920 B

__device__ __forceinline__ void mma16816(float c[4], uint32_t a0, uint32_t a1,
                                         uint32_t a2, uint32_t a3,
                                         uint32_t b0, uint32_t b1) {
    asm volatile(
        "mma.sync.aligned.m16n8k16.row.col.f32.bf16.bf16.f32 "
        "{%0,%1,%2,%3}, {%4,%5,%6,%7}, {%8,%9}, {%0,%1,%2,%3};"
        : "+f"(c[0]), "+f"(c[1]), "+f"(c[2]), "+f"(c[3])
        : "r"(a0), "r"(a1), "r"(a2), "r"(a3), "r"(b0), "r"(b1));
}

__global__ __launch_bounds__(GT, 1)
void gemm_mma_kernel(const float* __restrict__ bias,
                     float*       __restrict__ out) {
    extern __shared__ char smem[];
    const int t    = threadIdx.x;
    const int lane = t & 31;
    const int wid  = t >> 5;
    const int rowbase = blockIdx.x * 128;

    float* bias_s = reinterpret_cast<float*>(smem + SM_BIAS);
    __nv_bfloat16* Ahi = reinterpret_cast<__nv_bfloat16*>(smem + SM_AHI);
    __nv_bfloat16* Alo = reinterpret_cast<__nv_bfloat16*>(smem + SM_ALO);
    __nv_bfloat16* Bhi = reinterpret_cast<__nv_bfloat16*>(smem + SM_BHI);
    __nv_bfloat16* Blo = reinterpret_cast<__nv_bfloat16*>(smem + SM_BLO);

    if (t < 64)
        reinterpret_cast<float4*>(bias_s)[t] =
            reinterpret_cast<const float4*>(bias)[t];

    // Copy W^T hi/lo images: 2 x 4352 uint4, 17 per thread each.
    {
        const uint4* sh = reinterpret_cast<const uint4*>(g_Bhi);
        const uint4* sl = reinterpret_cast<const uint4*>(g_Blo);
        uint4* dh = reinterpret_cast<uint4*>(Bhi);
        uint4* dl = reinterpret_cast<uint4*>(Blo);
        #pragma unroll
        for (int i = 0; i < 17; i++) {
            dh[t + i * GT] = sh[t + i * GT];
            dl[t + i * GT] = sl[t + i * GT];
        }
    }

    // Load agg tile [128,128] fp32, split hi/lo bf16 into padded smem.
    // item = (m, kb): kb = 8-wide k block. 2048 items / 256 thr = 8 each.
    #pragma unroll
    for (int i = 0; i < 8; i++) {
        const int idx = t + i * GT;
        const int kb = idx & 15;
        const int m  = idx >> 4;
        const int row = rowbase + m;

        float f[8];
        if (row < N_NODES) {
            const float4* src = reinterpret_cast<const float4*>(
                g_agg + (size_t)row * IN_F + kb * 8);
            const float4 u = src[0];
            const float4 v = src[1];
            f[0]=u.x; f[1]=u.y; f[2]=u.z; f[3]=u.w;
            f[4]=v.x; f[5]=v.y; f[6]=v.z; f[7]=v.w;
        } else {
            #pragma unroll
            for (int j = 0; j < 8; j++) f[j] = 0.f;
        }

        uint4 wh, wl;
        uint32_t* ph = reinterpret_cast<uint32_t*>(&wh);
        uint32_t* pl = reinterpret_cast<uint32_t*>(&wl);
        #pragma unroll
        for (int j = 0; j < 4; j++) {
            const __nv_bfloat16 h0 = __float2bfloat16(f[2*j]);
            const __nv_bfloat16 h1 = __float2bfloat16(f[2*j+1]);
            const __nv_bfloat16 l0 = __float2bfloat16(f[2*j]   - __bfloat162float(h0));
            const __nv_bfloat16 l1 = __float2bfloat16(f[2*j+1] - __bfloat162float(h1));
            __nv_bfloat162 hp = __halves2bfloat162(h0, h1);
            __nv_bfloat162 lp = __halves2bfloat162(l0, l1);
            ph[j] = *reinterpret_cast<uint32_t*>(&hp);
            pl[j] = *reinterpret_cast<uint32_t*>(&lp);
        }
        *reinterpret_cast<uint4*>(Ahi + m * PITCH + kb * 8) = wh;
        *reinterpret_cast<uint4*>(Alo + m * PITCH + kb * 8) = wl;
    }
    __syncthreads();

    // Warp grid 2(m) x 4(n); warp tile 64x64.
    const int wm = wid >> 2;
    const int wn = wid & 3;
    const int g  = lane >> 2;     // group id 0..7
    const int tg = lane & 3;      // thread-in-group 0..3
    const int m_base = wm * 64;
    const int n_base = wn * 64;

    float acc[4][8][4];
    #pragma unroll
    for (int mt = 0; mt < 4; mt++)
        #pragma unroll
        for (int nt = 0; nt < 8; nt++)
            #pragma unroll
            for (int j = 0; j < 4; j++)
                acc[mt][nt][j] = 0.f;

    const __nv_bfloat16* Ap[3] = {Ahi, Ahi, Alo};
    const __nv_bfloat16* Bp[3] = {Bhi, Blo, Bhi};

    #pragma unroll
    for (int pass = 0; pass < 3; pass++) {
        const __nv_bfloat16* A = Ap[pass];
        const __nv_bfloat16* B = Bp[pass];
        #pragma unroll
        for (int ks = 0; ks < IN_F; ks += 16) {
            uint32_t af[4][4];
            #pragma unroll
            for (int mt = 0; mt < 4; mt++) {
                const __nv_bfloat16* ar =
                    A + (m_base + mt * 16 + g) * PITCH + ks + tg * 2;
                af[mt][0] = *reinterpret_cast<const uint32_t*>(ar);
                af[mt][1] = *reinterpret_cast<const uint32_t*>(ar + 8 * PITCH);
                af[mt][2] = *reinterpret_cast<const uint32_t*>(ar + 8);
                af[mt][3] = *reinterpret_cast<const uint32_t*>(ar + 8 * PITCH + 8);
            }
            uint32_t bf[8][2];
            #pragma unroll
            for (int nt = 0; nt < 8; nt++) {
                const __nv_bfloat16* br =
                    B + (n_base + nt * 8 + g) * PITCH + ks + tg * 2;
                bf[nt][0] = *reinterpret_cast<const uint32_t*>(br);
                bf[nt][1] = *reinterpret_cast<const uint32_t*>(br + 8);
            }
            #pragma unroll
            for (int mt = 0; mt < 4; mt++)
                #pragma unroll
                for (int nt = 0; nt < 8; nt++)
                    mma16816(acc[mt][nt],
                             af[mt][0], af[mt][1], af[mt][2], af[mt][3],
                             bf[nt][0], bf[nt][1]);
        }
    }

    // Epilogue: c0:(g,2t) c1:(g,2t+1) c2:(g+8,2t) c3:(g+8,2t+1)
    #pragma unroll
    for (int mt = 0; mt < 4; mt++) {
        const int r0 = rowbase + m_base + mt * 16 + g;
        const int r1 = r0 + 8;
        #pragma unroll
        for (int nt = 0; nt < 8; nt++) {
            const int col = n_base + nt * 8 + tg * 2;
            const float bx = bias_s[col];
            const float by = bias_s[col + 1];
            if (r0 < N_NODES) {
                float2 o = make_float2(acc[mt][nt][0] + bx, acc[mt][nt][1] + by);
                *reinterpret_cast<float2*>(out + (size_t)r0 * OUT_F + col) = o;
            }
            if (r1 < N_NODES) {
                float2 o = make_float2(acc[mt][nt][2] + bx, acc[mt][nt][3] + by);
                *reinterpret_cast<float2*>(out + (size_t)r1 * OUT_F + col) = o;
            }
        }
    }
}

// ---------------------------------------------------------------------------
// Launch
// ---------------------------------------------------------------------------
extern "C" void kernel_launch(void* const* d_in, const int* in_sizes, int n_in,
                              void* d_out, int out_size) {
    const float* x    = (const float*)d_in[0];
    const int*   erow = (const int*)  d_in[1];
    const int*   ecol = (const int*)  d_in[2];
    const float* eval = (const float*)d_in[3];
    const float* W    = (const float*)d_in[4];
    const float* bias = (const float*)d_in[5];
    float* out = (float*)d_out;

    prep_kernel<<<2048, 256>>>(W);

    const int warps_needed = (N_EDGES + EDGES_PER_WARP - 1) / EDGES_PER_WARP;
    const int spmm_blocks  = (warps_needed + 7) / 8;
    spmm_scatter_kernel<<<spmm_blocks, 256>>>(x, erow, ecol, eval);

    cudaFuncSetAttribute(gemm_mma_kernel,
                         cudaFuncAttributeMaxDynamicSharedMemorySize, SM_TOT);
    const int gemm_blocks = (N_NODES + 127) / 128;   // 391
    gemm_mma_kernel<<<gemm_blocks, GT, SM_TOT>>>(bias, out);
}